// round 9
// baseline (speedup 1.0000x reference)
#include <cuda_runtime.h>

// DotAttention: rnn_out [S,B,H] f32, state [2,2,B,H/2] f32 -> out [B,H,1] f32
// S=2048, B=32, H=1024.
// pass1: flash-style online-softmax partials; one warp per (b, 32-row chunk),
//        register-resident merged vector, 4-way split dot chain, warp-uniform
//        branch skips acc rescale when the max doesn't change. 8 warps/CTA
//        combine in smem -> one partial per CTA (256 CTAs, 1MB scratch).
// pass2: fused combine + weighted sum over 8 partials/batch, 64 CTAs.

#define S_LEN 2048
#define B_DIM 32
#define H_DIM 1024
#define SPLIT 64
#define CHUNK (S_LEN / SPLIT)          // 32 rows per warp
#define WARPS_PER_CTA 8
#define NCTA  (B_DIM * SPLIT / WARPS_PER_CTA)   // 256 CTAs
#define PPB   (SPLIT / WARPS_PER_CTA)           // 8 partials per batch

__device__ float g_m[NCTA];
__device__ float g_l[NCTA];
__device__ float g_acc[(size_t)NCTA * H_DIM];   // 1 MB scratch (L2-resident)

__global__ __launch_bounds__(256) void pass1(const float* __restrict__ rnn,
                                             const float* __restrict__ state) {
    const int tid  = threadIdx.x;
    const int lane = tid & 31;
    const int wid  = tid >> 5;
    const int warp  = blockIdx.x * WARPS_PER_CTA + wid;
    const int b     = warp / SPLIT;
    const int chunk = warp % SPLIT;

    // merged[b, h]: h = j*128 + lane*4; direction = h>>9
    float4 mrg[8];
#pragma unroll
    for (int j = 0; j < 8; j++) {
        int h = j * 128 + lane * 4;
        int d = h >> 9;
        int hh = h & 511;
        mrg[j] = *reinterpret_cast<const float4*>(
            state + (size_t)(2 + d) * B_DIM * 512 + (size_t)b * 512 + hh);
    }

    float4 acc[8];
#pragma unroll
    for (int j = 0; j < 8; j++) acc[j] = make_float4(0.f, 0.f, 0.f, 0.f);
    float m = -1e30f, l = 0.f;

    const float* base = rnn + (size_t)(chunk * CHUNK) * (B_DIM * H_DIM)
                            + (size_t)b * H_DIM;

    for (int s = 0; s < CHUNK; s++) {
        const float4* row =
            reinterpret_cast<const float4*>(base + (size_t)s * (B_DIM * H_DIM));
        float4 x[8];
#pragma unroll
        for (int j = 0; j < 8; j++) x[j] = row[j * 32 + lane];

        // 4-way split dot chain (shorter serial dependency)
        float p0 = 0.f, p1 = 0.f, p2 = 0.f, p3 = 0.f;
#pragma unroll
        for (int j = 0; j < 8; j += 4) {
            p0 += x[j+0].x * mrg[j+0].x + x[j+0].y * mrg[j+0].y +
                  x[j+0].z * mrg[j+0].z + x[j+0].w * mrg[j+0].w;
            p1 += x[j+1].x * mrg[j+1].x + x[j+1].y * mrg[j+1].y +
                  x[j+1].z * mrg[j+1].z + x[j+1].w * mrg[j+1].w;
            p2 += x[j+2].x * mrg[j+2].x + x[j+2].y * mrg[j+2].y +
                  x[j+2].z * mrg[j+2].z + x[j+2].w * mrg[j+2].w;
            p3 += x[j+3].x * mrg[j+3].x + x[j+3].y * mrg[j+3].y +
                  x[j+3].z * mrg[j+3].z + x[j+3].w * mrg[j+3].w;
        }
        float p = (p0 + p1) + (p2 + p3);
#pragma unroll
        for (int off = 16; off > 0; off >>= 1)
            p += __shfl_xor_sync(0xffffffffu, p, off);

        // p is bitwise-identical across lanes -> uniform branch
        if (p > m) {
            float scale = __expf(m - p);
#pragma unroll
            for (int j = 0; j < 8; j++) {
                acc[j].x *= scale; acc[j].y *= scale;
                acc[j].z *= scale; acc[j].w *= scale;
            }
            l *= scale;
            m = p;
        }
        float w = __expf(p - m);
#pragma unroll
        for (int j = 0; j < 8; j++) {
            acc[j].x += w * x[j].x;
            acc[j].y += w * x[j].y;
            acc[j].z += w * x[j].z;
            acc[j].w += w * x[j].w;
        }
        l += w;
    }

    // ---- CTA-level combine of the 8 warps' partials ----
    __shared__ float s_m[WARPS_PER_CTA], s_l[WARPS_PER_CTA];
    __shared__ float4 sbuf[WARPS_PER_CTA][256];   // 32 KB

    if (lane == 0) { s_m[wid] = m; s_l[wid] = l; }
    __syncthreads();

    float M = s_m[0];
#pragma unroll
    for (int k = 1; k < WARPS_PER_CTA; k++) M = fmaxf(M, s_m[k]);
    float sc = __expf(m - M);

#pragma unroll
    for (int j = 0; j < 8; j++) {
        sbuf[wid][j * 32 + lane] =
            make_float4(acc[j].x * sc, acc[j].y * sc, acc[j].z * sc, acc[j].w * sc);
    }
    __syncthreads();

    // warp `wid` reduces j-group `wid` across the 8 staged buffers
    float4 r = make_float4(0.f, 0.f, 0.f, 0.f);
#pragma unroll
    for (int k = 0; k < WARPS_PER_CTA; k++) {
        float4 a = sbuf[k][wid * 32 + lane];
        r.x += a.x; r.y += a.y; r.z += a.z; r.w += a.w;
    }

    float4* out4 = reinterpret_cast<float4*>(g_acc + (size_t)blockIdx.x * H_DIM);
    out4[wid * 32 + lane] = r;

    if (tid == 0) {
        float L = 0.f;
#pragma unroll
        for (int k = 0; k < WARPS_PER_CTA; k++)
            L += s_l[k] * __expf(s_m[k] - M);
        g_m[blockIdx.x] = M;
        g_l[blockIdx.x] = L;
    }
}

// Combine + weighted sum over PPB=8 partials per batch. grid = (2, 32).
__global__ __launch_bounds__(128) void pass2(float* __restrict__ out) {
    const int half = blockIdx.x;         // 0..1 (512 h each)
    const int b    = blockIdx.y;         // 0..31
    const int tid  = threadIdx.x;        // owns one float4

    float mv[PPB], lv[PPB];
#pragma unroll
    for (int k = 0; k < PPB; k++) {
        mv[k] = g_m[b * PPB + k];
        lv[k] = g_l[b * PPB + k];
    }
    float M = mv[0];
#pragma unroll
    for (int k = 1; k < PPB; k++) M = fmaxf(M, mv[k]);
    float L = 0.f;
    float w[PPB];
#pragma unroll
    for (int k = 0; k < PPB; k++) {
        w[k] = __expf(mv[k] - M);
        L += lv[k] * w[k];
    }
    float inv = 1.f / L;

    const float* bse = g_acc + ((size_t)b * PPB) * H_DIM + half * 512 + tid * 4;
    float rx = 0.f, ry = 0.f, rz = 0.f, rw = 0.f;
#pragma unroll
    for (int k = 0; k < PPB; k++) {
        float4 a = *reinterpret_cast<const float4*>(bse + (size_t)k * H_DIM);
        rx += w[k] * a.x; ry += w[k] * a.y; rz += w[k] * a.z; rw += w[k] * a.w;
    }
    reinterpret_cast<float4*>(out)[(b * H_DIM + half * 512) / 4 + tid] =
        make_float4(rx * inv, ry * inv, rz * inv, rw * inv);
}

extern "C" void kernel_launch(void* const* d_in, const int* in_sizes, int n_in,
                              void* d_out, int out_size) {
    const float* rnn   = (const float*)d_in[0];
    const float* state = (const float*)d_in[1];
    float* out         = (float*)d_out;

    pass1<<<NCTA, 256>>>(rnn, state);
    dim3 g2(2, B_DIM);
    pass2<<<g2, 128>>>(out);
}